// round 15
// baseline (speedup 1.0000x reference)
#include <cuda_runtime.h>
#include <cuda_bf16.h>
#include <math.h>

// ---------------------------------------------------------------------------
// Problem constants
// ---------------------------------------------------------------------------
#define NLEV 16
#define TSZ  (1 << 19)
#define TMASK (TSZ - 1)
#define HASH_PRIME 2654435761u

typedef unsigned long long u64;

// Padded weight blob: wp1[12*64] | wp2[64*64] | wp3[64] | wt[32*68] | bt[68]
#define OFF_WP1 0
#define OFF_WP2 768
#define OFF_WP3 4864
#define OFF_WT  4928
#define OFF_BT  7104
#define TOTW    7172

struct __align__(16) Weights {
    float wp1[12 * 64];
    float wp2[64 * 64];
    float wp3[64];
    float wt [32 * 68];
    float bt [68];
};
__device__ Weights g_w;

struct LevelP {
    float scale[NLEV];
    int   res[NLEV];
    int   dense[NLEV];
};

// Tile/block geometry
#define TPB   384          // threads per block
#define TILE  192          // points per block
#define NPG   24           // point groups (8 pts each)

// Shared layout (floats); ACT_STRIDE mod 32 == 4 (same bank rotation as 132)
#define ACT_STRIDE 196
#define ACT_ROWS   65                       // 64 + prefetch slack
#define ACT_FLOATS (ACT_ROWS * ACT_STRIDE)  // 12740 (out-stage 192*65=12480 fits)
#define FEAT_ROWS  33                       // 32 + prefetch slack
#define FEAT_FLOATS (FEAT_ROWS * ACT_STRIDE)// 6468
#define SM_ACT   TOTW
#define SM_FEAT  (SM_ACT + ACT_FLOATS)
#define SM_Z     (SM_FEAT + FEAT_FLOATS)    // 192
#define SM_X64   (SM_Z + TILE)              // 384 (two halves)
#define SM_PZ    (SM_X64 + 2 * TILE)        // 192
#define SMEM_FLOATS (SM_PZ + TILE)
#define SMEM_BYTES  (SMEM_FLOATS * 4)       // 108,592 B = 106.0 KB -> 2 blocks/SM

// ---------------------------------------------------------------------------
// f32x2 helpers
// ---------------------------------------------------------------------------
__device__ __forceinline__ u64 dup2(float a) {
    u64 r; asm("mov.b64 %0, {%1, %1};" : "=l"(r) : "f"(a)); return r;
}
__device__ __forceinline__ u64 pack2(float a, float b) {
    u64 r; asm("mov.b64 %0, {%1, %2};" : "=l"(r) : "f"(a), "f"(b)); return r;
}
__device__ __forceinline__ void unpack2(u64 v, float &a, float &b) {
    asm("mov.b64 {%0, %1}, %2;" : "=f"(a), "=f"(b) : "l"(v));
}
__device__ __forceinline__ void fma2(u64 &d, u64 a, u64 b) {
    asm("fma.rn.f32x2 %0, %1, %2, %0;" : "+l"(d) : "l"(a), "l"(b));
}
__device__ __forceinline__ float sigm(float x) {
    return __fdividef(1.0f, 1.0f + __expf(-x));
}

// ---------------------------------------------------------------------------
// Register-tiled GEMM accumulate with k+1 prefetch (champion structure).
// Thread (pg,cg): points [pg*8,+8) x cols [cg*4,+4);  acc[p2*4+c].
// Prefetch reads one row past K — lands in valid smem slack (value unused).
// B prefetch past the last row lands inside the contiguous weight blob.
// ---------------------------------------------------------------------------
template <int K, int NC>
__device__ __forceinline__ void gemm_acc(u64* __restrict__ acc,
                                         const float* __restrict__ aT,
                                         const float* __restrict__ B,
                                         int pg, int cg) {
    const float* arow = aT + pg * 8;
    const float* brow = B + cg * 4;
    ulonglong2 a01 = *reinterpret_cast<const ulonglong2*>(arow);
    ulonglong2 a23 = *reinterpret_cast<const ulonglong2*>(arow + 4);
    float4 b4 = *reinterpret_cast<const float4*>(brow);
    #pragma unroll 8
    for (int k = 0; k < K; k++) {
        const float* an = arow + (k + 1) * ACT_STRIDE;
        ulonglong2 na01 = *reinterpret_cast<const ulonglong2*>(an);
        ulonglong2 na23 = *reinterpret_cast<const ulonglong2*>(an + 4);
        float4 nb4 = *reinterpret_cast<const float4*>(brow + (k + 1) * NC);
        u64 b0 = dup2(b4.x), b1 = dup2(b4.y), b2 = dup2(b4.z), b3 = dup2(b4.w);
        u64 a[4] = {a01.x, a01.y, a23.x, a23.y};
        #pragma unroll
        for (int p = 0; p < 4; p++) {
            fma2(acc[p * 4 + 0], a[p], b0);
            fma2(acc[p * 4 + 1], a[p], b1);
            fma2(acc[p * 4 + 2], a[p], b2);
            fma2(acc[p * 4 + 3], a[p], b3);
        }
        a01 = na01; a23 = na23; b4 = nb4;
    }
}

// ---------------------------------------------------------------------------
// Prep kernel: pack weights into padded blob
// ---------------------------------------------------------------------------
__global__ void prep_weights(const float* __restrict__ W_tiny,
                             const float* __restrict__ b_tiny,
                             const float* __restrict__ Wp1,
                             const float* __restrict__ Wp2,
                             const float* __restrict__ Wp3) {
    int t = threadIdx.x;
    for (int i = t; i < 12 * 64; i += blockDim.x) g_w.wp1[i] = Wp1[i];
    for (int i = t; i < 64 * 64; i += blockDim.x) g_w.wp2[i] = Wp2[i];
    if (t < 64) g_w.wp3[t] = Wp3[t];
    for (int i = t; i < 32 * 68; i += blockDim.x) {
        int k = i / 68, j = i % 68;
        g_w.wt[i] = (j < 65) ? W_tiny[k * 65 + j] : 0.0f;
    }
    if (t < 68) g_w.bt[t] = (t < 65) ? b_tiny[t] : 0.0f;
}

// ---------------------------------------------------------------------------
// Fused kernel: 192-pt tile, 384 threads, shuffle prior, 24 warps/SM target
// ---------------------------------------------------------------------------
__global__ void __launch_bounds__(TPB, 2)
sdf_kernel(const float* __restrict__ inputs,
           const float* __restrict__ tables,
           float* __restrict__ out,
           int N, LevelP P) {
    extern __shared__ float smem[];
    float* sw    = smem;                      // weights blob (28.7 KB)
    float* actT  = smem + SM_ACT;             // encT rows 0-11 / h1T rows 0-63 / out-stage
    float* featT = smem + SM_FEAT;            // [32+1][196]
    float* sZ    = smem + SM_Z;               // [192]
    float* sX64  = smem + SM_X64;             // [384] (two halves)
    float* sPZ   = smem + SM_PZ;              // [192]

    const int tid = threadIdx.x;
    const int pg  = tid >> 4;                 // 0..23 point-groups of 8 pts
    const int cg  = tid & 15;                 // 0..15 col-groups of 4 cols
    const int base = blockIdx.x * TILE;
    const int cnt  = min(TILE, N - base);

    // ---- cooperative weight load ----
    {
        const float4* src = reinterpret_cast<const float4*>(g_w.wp1);
        float4* dst = reinterpret_cast<float4*>(sw);
        #pragma unroll
        for (int i = tid; i < TOTW / 4; i += TPB) dst[i] = src[i];
    }
    __syncthreads();

    // =======================================================================
    // Split scalar phase: 2 threads per point (warps 0-5 half0, 6-11 half1)
    //   half 0 -> x-sincos (encT rows 0-5)  + even hash levels
    //   half 1 -> y-sincos (encT rows 6-11) + odd  hash levels
    // =======================================================================
    {
        const int half = (tid >= TILE) ? 1 : 0;
        const int p    = tid - half * TILE;
        float x = 0.f, y = 0.f;
        if (p < cnt) {
            const float* ip = inputs + (size_t)(base + p) * 3;
            x = ip[0]; y = ip[1];
            if (half == 0) sZ[p] = ip[2];
        } else if (half == 0) sZ[p] = 0.f;

        // sincos for this half's coordinate
        {
            const float PIF = 3.14159265358979323846f;
            const float cc = (half == 0) ? x : y;
            float s0, c0, s1, c1, s2, c2;
            sincosf(cc * PIF,          &s0, &c0);
            sincosf(cc * (2.0f * PIF), &s1, &c1);
            sincosf(cc * (4.0f * PIF), &s2, &c2);
            float* eb = actT + half * 6 * ACT_STRIDE + p;
            if (p < cnt) {
                eb[0 * ACT_STRIDE] = s0; eb[1 * ACT_STRIDE] = s1; eb[2 * ACT_STRIDE] = s2;
                eb[3 * ACT_STRIDE] = c0; eb[4 * ACT_STRIDE] = c1; eb[5 * ACT_STRIDE] = c2;
            } else {
                eb[0 * ACT_STRIDE] = 0.f; eb[1 * ACT_STRIDE] = 0.f; eb[2 * ACT_STRIDE] = 0.f;
                eb[3 * ACT_STRIDE] = 0.f; eb[4 * ACT_STRIDE] = 0.f; eb[5 * ACT_STRIDE] = 0.f;
            }
        }

        // 8 hash levels (parity split), featT written in-loop, x64 incremental
        float x64 = 0.0f;
        if (p < cnt) {
            const float u = __fadd_rn(__fdiv_rn(x, 30.0f), 0.5f);
            const float v = __fadd_rn(__fdiv_rn(y, 30.0f), 0.5f);
            const float2* tb = reinterpret_cast<const float2*>(tables);
            #pragma unroll
            for (int i = 0; i < 8; i++) {
                const int l = 2 * i + half;
                float s  = P.scale[l];
                float px = __fadd_rn(__fmul_rn(u, s), 0.5f);
                float py = __fadd_rn(__fmul_rn(v, s), 0.5f);
                float fx = floorf(px), fy = floorf(py);
                float wx = px - fx,    wy = py - fy;
                int ix = (int)fx, iy = (int)fy;
                int i00, i10, i01, i11;
                if (P.dense[l]) {
                    int r = P.res[l];
                    i00 = ix + iy * r;  i10 = i00 + 1;
                    i01 = i00 + r;      i11 = i01 + 1;
                    i00 = min(max(i00, 0), TSZ - 1);
                    i10 = min(max(i10, 0), TSZ - 1);
                    i01 = min(max(i01, 0), TSZ - 1);
                    i11 = min(max(i11, 0), TSZ - 1);
                } else {
                    unsigned ux = (unsigned)ix, uy = (unsigned)iy;
                    unsigned hy0 = uy * HASH_PRIME;
                    unsigned hy1 = (uy + 1u) * HASH_PRIME;
                    i00 = (int)((ux        ^ hy0) & TMASK);
                    i10 = (int)(((ux + 1u) ^ hy0) & TMASK);
                    i01 = (int)((ux        ^ hy1) & TMASK);
                    i11 = (int)(((ux + 1u) ^ hy1) & TMASK);
                }
                const float2* t = tb + (size_t)l * TSZ;
                float2 f00 = __ldg(t + i00);
                float2 f10 = __ldg(t + i10);
                float2 f01 = __ldg(t + i01);
                float2 f11 = __ldg(t + i11);
                float omx = 1.0f - wx, omy = 1.0f - wy;
                float g0 = (f00.x * omx + f10.x * wx) * omy + (f01.x * omx + f11.x * wx) * wy;
                float g1 = (f00.y * omx + f10.y * wx) * omy + (f01.y * omx + f11.y * wx) * wy;
                featT[(2 * l) * ACT_STRIDE + p]     = g0;
                featT[(2 * l + 1) * ACT_STRIDE + p] = g1;
                x64 += g0 * sw[OFF_WT + (2 * l) * 68 + 64];
                x64 += g1 * sw[OFF_WT + (2 * l + 1) * 68 + 64];
            }
        } else {
            #pragma unroll
            for (int i = 0; i < 8; i++) {
                const int l = 2 * i + half;
                featT[(2 * l) * ACT_STRIDE + p]     = 0.f;
                featT[(2 * l + 1) * ACT_STRIDE + p] = 0.f;
            }
        }
        sX64[half * TILE + p] = x64;
    }
    __syncthreads();

    u64 acc[16];

    // ---- GEMM1: h1 = sigmoid(enc @ Wp1)  [192,12]x[12,64] ----
    #pragma unroll
    for (int q = 0; q < 16; q++) acc[q] = 0ull;
    gemm_acc<12, 64>(acc, actT, sw + OFF_WP1, pg, cg);
    __syncthreads();                          // encT reads done; actT -> h1T
    #pragma unroll
    for (int c = 0; c < 4; c++) {
        float* row = actT + (cg * 4 + c) * ACT_STRIDE + pg * 8;
        #pragma unroll
        for (int p2 = 0; p2 < 4; p2++) {
            float a, b; unpack2(acc[p2 * 4 + c], a, b);
            *reinterpret_cast<u64*>(row + 2 * p2) = pack2(sigm(a), sigm(b));
        }
    }
    __syncthreads();

    // ---- GEMM2: h2 = sigmoid(h1 @ Wp2); prior via half-warp shuffle ----
    #pragma unroll
    for (int q = 0; q < 16; q++) acc[q] = 0ull;
    gemm_acc<64, 64>(acc, actT, sw + OFF_WP2, pg, cg);
    {
        float pp[8];
        #pragma unroll
        for (int i = 0; i < 8; i++) pp[i] = 0.f;
        #pragma unroll
        for (int c = 0; c < 4; c++) {
            const float w3 = sw[OFF_WP3 + cg * 4 + c];
            #pragma unroll
            for (int p2 = 0; p2 < 4; p2++) {
                float a, b; unpack2(acc[p2 * 4 + c], a, b);
                pp[2 * p2]     += sigm(a) * w3;
                pp[2 * p2 + 1] += sigm(b) * w3;
            }
        }
        // reduce across the 16 cg-lanes (a contiguous half-warp shares pg)
        #pragma unroll
        for (int m = 1; m < 16; m <<= 1) {
            #pragma unroll
            for (int i = 0; i < 8; i++)
                pp[i] += __shfl_xor_sync(0xFFFFFFFFu, pp[i], m);
        }
        if (cg == 0) {
            const float bt0 = sw[OFF_BT];
            #pragma unroll
            for (int i = 0; i < 8; i++) {
                const int pt = pg * 8 + i;
                sPZ[pt] = (sZ[pt] - bt0) - pp[i];     // z - bt0 - prior
            }
        }
    }

    // ---- x64 combine (subset of threads) + GEMM3: feat @ wt[:,0:64] ----
    if (tid < TILE)
        sX64[tid] = sX64[tid] + sX64[TILE + tid] + sw[OFF_BT + 64];
    #pragma unroll
    for (int q = 0; q < 16; q++) acc[q] = 0ull;
    gemm_acc<32, 68>(acc, featT, sw + OFF_WT, pg, cg);
    __syncthreads();                          // featT/h1T dead; sPZ/sX64 ready

    // ---- assemble output rows [192][65] in shared (actT region) ----
    {
        float* ost = actT;
        #pragma unroll
        for (int c = 0; c < 4; c++) {
            const int col = cg * 4 + c;
            const float bias = sw[OFF_BT + col];
            #pragma unroll
            for (int p2 = 0; p2 < 4; p2++) {
                float a, b; unpack2(acc[p2 * 4 + c], a, b);
                int pA = pg * 8 + 2 * p2;
                if (col == 0) {
                    ost[pA * 65]       = sPZ[pA] - a;
                    ost[(pA + 1) * 65] = sPZ[pA + 1] - b;
                } else {
                    ost[pA * 65 + col]       = a + bias;
                    ost[(pA + 1) * 65 + col] = b + bias;
                }
            }
        }
        if (tid < TILE) ost[tid * 65 + 64] = sX64[tid];
    }
    __syncthreads();

    // ---- coalesced flush ----
    if (cnt == TILE) {
        float4* o4 = reinterpret_cast<float4*>(out + (size_t)base * 65);
        const float4* s4 = reinterpret_cast<const float4*>(actT);
        #pragma unroll
        for (int t = tid; t < (TILE * 65) / 4; t += TPB) o4[t] = s4[t];
    } else if (cnt > 0) {
        const int tot = cnt * 65;
        for (int t = tid; t < tot; t += TPB) out[(size_t)base * 65 + t] = actT[t];
    }
}

// ---------------------------------------------------------------------------
// Launch
// ---------------------------------------------------------------------------
extern "C" void kernel_launch(void* const* d_in, const int* in_sizes, int n_in,
                              void* d_out, int out_size) {
    const float* inputs  = (const float*)d_in[0];
    const float* tables  = (const float*)d_in[1];
    const float* W_tiny  = (const float*)d_in[2];
    const float* b_tiny  = (const float*)d_in[3];
    const float* Wp1     = (const float*)d_in[4];
    const float* Wp2     = (const float*)d_in[5];
    const float* Wp3     = (const float*)d_in[6];
    float* out           = (float*)d_out;

    const int N = in_sizes[0] / 3;

    LevelP P;
    for (int l = 0; l < NLEV; l++) {
        double sc = pow(2.0, (double)l * log2(1.5)) * 16.0 - 1.0;
        int res = (int)ceil(sc) + 1;
        P.scale[l] = (float)sc;
        P.res[l]   = res;
        P.dense[l] = ((long long)res * (long long)res <= (long long)TSZ) ? 1 : 0;
    }

    prep_weights<<<1, 256>>>(W_tiny, b_tiny, Wp1, Wp2, Wp3);

    static int attr_done = 0;
    if (!attr_done) {
        cudaFuncSetAttribute(sdf_kernel,
                             cudaFuncAttributeMaxDynamicSharedMemorySize, SMEM_BYTES);
        attr_done = 1;
    }

    const int tiles = (N + TILE - 1) / TILE;
    sdf_kernel<<<tiles, TPB, SMEM_BYTES>>>(inputs, tables, out, N, P);
}

// round 16
// speedup vs baseline: 1.1683x; 1.1683x over previous
#include <cuda_runtime.h>
#include <cuda_bf16.h>
#include <math.h>

// ---------------------------------------------------------------------------
// Problem constants
// ---------------------------------------------------------------------------
#define NLEV 16
#define TSZ  (1 << 19)
#define TMASK (TSZ - 1)
#define HASH_PRIME 2654435761u

typedef unsigned long long u64;

// Weight blob: wp1[12*64] | wp2[64*64] | wp3[64] | wt[32*68] | bt[68]
#define OFF_WP1 0
#define OFF_WP2 768
#define OFF_WP3 4864
#define OFF_WT  4928
#define OFF_BT  7104
#define TOTW    7172

struct __align__(16) Weights {
    float wp1[12 * 64];
    float wp2[64 * 64];
    float wp3[64];
    float wt [32 * 68];
    float bt [68];
};
__device__ Weights g_w;

struct LevelP {
    float scale[NLEV];
    int   res[NLEV];
    int   dense[NLEV];
};

// Shared layout (floats), stride 132 (R10 layout)
#define ACT_STRIDE 132
#define ACT_FLOATS  (64 * ACT_STRIDE)     // 8448: encT rows0-11 / h1T rows0-63 / out-stage 128x65
#define FEAT_FLOATS (33 * ACT_STRIDE)     // 4356 (row 32 = prefetch slack)
#define SM_FEAT  (TOTW + ACT_FLOATS)
#define SM_Z     (SM_FEAT + FEAT_FLOATS)  // 128
#define SM_X64   (SM_Z + 128)             // 128
#define SM_PZ    (SM_X64 + 128)           // 128
#define SMEM_FLOATS (SM_PZ + 128)
#define SMEM_BYTES  (SMEM_FLOATS * 4)

// ---------------------------------------------------------------------------
// f32x2 helpers
// ---------------------------------------------------------------------------
__device__ __forceinline__ u64 dup2(float a) {
    u64 r; asm("mov.b64 %0, {%1, %1};" : "=l"(r) : "f"(a)); return r;
}
__device__ __forceinline__ u64 pack2(float a, float b) {
    u64 r; asm("mov.b64 %0, {%1, %2};" : "=l"(r) : "f"(a), "f"(b)); return r;
}
__device__ __forceinline__ void unpack2(u64 v, float &a, float &b) {
    asm("mov.b64 {%0, %1}, %2;" : "=f"(a), "=f"(b) : "l"(v));
}
__device__ __forceinline__ void fma2(u64 &d, u64 a, u64 b) {
    asm("fma.rn.f32x2 %0, %1, %2, %0;" : "+l"(d) : "l"(a), "l"(b));
}
__device__ __forceinline__ float sigm(float x) {
    return __fdividef(1.0f, 1.0f + __expf(-x));
}
__device__ __forceinline__ void bar_crew0() {
    asm volatile("bar.sync 1, 128;" ::: "memory");
}
__device__ __forceinline__ void bar_crew1() {
    asm volatile("bar.sync 2, 128;" ::: "memory");
}

// ---------------------------------------------------------------------------
// 8pt x 8col register-tiled GEMM for a 128-thread crew (R10-proven):
//   pgA = m>>3 (0..15), cgA = m&7 (0..7) -> cols cgA*8..+8
//   acc[p2*8+c]; A prefetched (k+1 reads slack row / adjacent valid smem).
// Per warp per k: A 2x1 wf + B 2x1 wf = 4 wf for 32 fma2/thread.
// ---------------------------------------------------------------------------
template <int K, int NC, int UNR>
__device__ __forceinline__ void gemm88(u64* __restrict__ acc,
                                       const float* __restrict__ aT,
                                       const float* __restrict__ B,
                                       int pgA, int cgA) {
    const float* arow = aT + pgA * 8;
    const float* brow = B + cgA * 8;
    ulonglong2 a01 = *reinterpret_cast<const ulonglong2*>(arow);
    ulonglong2 a23 = *reinterpret_cast<const ulonglong2*>(arow + 4);
    #pragma unroll UNR
    for (int k = 0; k < K; k++) {
        const float* an = arow + (k + 1) * ACT_STRIDE;
        ulonglong2 na01 = *reinterpret_cast<const ulonglong2*>(an);
        ulonglong2 na23 = *reinterpret_cast<const ulonglong2*>(an + 4);
        float4 b0 = *reinterpret_cast<const float4*>(brow + k * NC);
        float4 b1 = *reinterpret_cast<const float4*>(brow + k * NC + 4);
        u64 a[4] = {a01.x, a01.y, a23.x, a23.y};
        float bf[8] = {b0.x, b0.y, b0.z, b0.w, b1.x, b1.y, b1.z, b1.w};
        #pragma unroll
        for (int c = 0; c < 8; c++) {
            u64 bb = dup2(bf[c]);
            fma2(acc[0 * 8 + c], a[0], bb);
            fma2(acc[1 * 8 + c], a[1], bb);
            fma2(acc[2 * 8 + c], a[2], bb);
            fma2(acc[3 * 8 + c], a[3], bb);
        }
        a01 = na01; a23 = na23;
    }
}

// ---------------------------------------------------------------------------
// Prep kernel
// ---------------------------------------------------------------------------
__global__ void prep_weights(const float* __restrict__ W_tiny,
                             const float* __restrict__ b_tiny,
                             const float* __restrict__ Wp1,
                             const float* __restrict__ Wp2,
                             const float* __restrict__ Wp3) {
    int t = threadIdx.x;
    for (int i = t; i < 12 * 64; i += blockDim.x) g_w.wp1[i] = Wp1[i];
    for (int i = t; i < 64 * 64; i += blockDim.x) g_w.wp2[i] = Wp2[i];
    if (t < 64) g_w.wp3[t] = Wp3[t];
    for (int i = t; i < 32 * 68; i += blockDim.x) {
        int k = i / 68, j = i % 68;
        g_w.wt[i] = (j < 65) ? W_tiny[k * 65 + j] : 0.0f;
    }
    if (t < 68) g_w.bt[t] = (t < 65) ? b_tiny[t] : 0.0f;
}

// ---------------------------------------------------------------------------
// Fused kernel:
//   crew0 (0-127):  encode -> GEMM1 -> GEMM2 -> prior(shuffle) -> sPZ
//   crew1 (128-255): hash gather -> GEMM3 (overlapped with crew0's GEMM2)
//   join -> crew1 assembly -> flush (all)
// ---------------------------------------------------------------------------
__global__ void __launch_bounds__(256, 2)
sdf_kernel(const float* __restrict__ inputs,
           const float* __restrict__ tables,
           float* __restrict__ out,
           int N, LevelP P) {
    extern __shared__ float smem[];
    float* sw    = smem;
    float* actT  = smem + TOTW;       // encT / h1T / out-stage
    float* featT = smem + SM_FEAT;
    float* sZ    = smem + SM_Z;
    float* sX64  = smem + SM_X64;
    float* sPZ   = smem + SM_PZ;

    const int tid  = threadIdx.x;
    const int base = blockIdx.x * 128;
    const int cnt  = min(128, N - base);

    // ---- cooperative weight load ----
    {
        const float4* src = reinterpret_cast<const float4*>(g_w.wp1);
        float4* dst = reinterpret_cast<float4*>(sw);
        #pragma unroll
        for (int i = tid; i < TOTW / 4; i += 256) dst[i] = src[i];
    }
    __syncthreads();

    u64 acc3[32];                     // crew1's GEMM3 accumulator (held to assembly)

    if (tid < 128) {
        // ============================ CREW 0 =================================
        const int pgA = tid >> 3;     // 0..15
        const int cgA = tid & 7;      // 0..7

        // encode own point
        {
            float x = 0.f, y = 0.f, z = 0.f;
            if (tid < cnt) {
                const float* ip = inputs + (size_t)(base + tid) * 3;
                x = ip[0]; y = ip[1]; z = ip[2];
            }
            const float PIF = 3.14159265358979323846f;
            float s, c, e[12];
            sincosf(x * PIF,          &s, &c); e[0] = s; e[3]  = c;
            sincosf(x * (2.0f * PIF), &s, &c); e[1] = s; e[4]  = c;
            sincosf(x * (4.0f * PIF), &s, &c); e[2] = s; e[5]  = c;
            sincosf(y * PIF,          &s, &c); e[6] = s; e[9]  = c;
            sincosf(y * (2.0f * PIF), &s, &c); e[7] = s; e[10] = c;
            sincosf(y * (4.0f * PIF), &s, &c); e[8] = s; e[11] = c;
            #pragma unroll
            for (int i = 0; i < 12; i++)
                actT[i * ACT_STRIDE + tid] = (tid < cnt) ? e[i] : 0.0f;
            sZ[tid] = z;
        }
        bar_crew0();                  // encT complete

        u64 acc8[32];

        // --- GEMM1: h1 = sigmoid(enc @ Wp1) ---
        #pragma unroll
        for (int q = 0; q < 32; q++) acc8[q] = 0ull;
        gemm88<12, 64, 12>(acc8, actT, sw + OFF_WP1, pgA, cgA);
        bar_crew0();                  // encT reads done -> overwrite as h1T
        #pragma unroll
        for (int c = 0; c < 8; c++) {
            float* rw = actT + (cgA * 8 + c) * ACT_STRIDE + pgA * 8;
            #pragma unroll
            for (int p2 = 0; p2 < 4; p2++) {
                float a, b; unpack2(acc8[p2 * 8 + c], a, b);
                *reinterpret_cast<u64*>(rw + 2 * p2) = pack2(sigm(a), sigm(b));
            }
        }
        bar_crew0();                  // h1T visible

        // --- GEMM2: h2 = sigmoid(h1 @ Wp2); prior via warp shuffle ---
        #pragma unroll
        for (int q = 0; q < 32; q++) acc8[q] = 0ull;
        gemm88<64, 64, 8>(acc8, actT, sw + OFF_WP2, pgA, cgA);
        {
            float pp[8];
            #pragma unroll
            for (int i = 0; i < 8; i++) pp[i] = 0.f;
            #pragma unroll
            for (int c = 0; c < 8; c++) {
                const float w3 = sw[OFF_WP3 + cgA * 8 + c];
                #pragma unroll
                for (int p2 = 0; p2 < 4; p2++) {
                    float a, b; unpack2(acc8[p2 * 8 + c], a, b);
                    pp[2 * p2]     += sigm(a) * w3;
                    pp[2 * p2 + 1] += sigm(b) * w3;
                }
            }
            // reduce over the 8 cgA lanes (lanes sharing pgA are 8 consecutive)
            #pragma unroll
            for (int m = 1; m < 8; m <<= 1) {
                #pragma unroll
                for (int i = 0; i < 8; i++)
                    pp[i] += __shfl_xor_sync(0xFFFFFFFFu, pp[i], m);
            }
            if (cgA == 0) {
                const float bt0 = sw[OFF_BT];
                #pragma unroll
                for (int i = 0; i < 8; i++) {
                    const int pt = pgA * 8 + i;
                    sPZ[pt] = (sZ[pt] - bt0) - pp[i];     // z - bt0 - prior
                }
            }
        }
    } else {
        // ============================ CREW 1 =================================
        const int m   = tid - 128;
        const int pgB = m >> 3;       // 0..15
        const int cgB = m & 7;        // 0..7

        // hash gather: full 16 levels for own point
        {
            const int p = m;
            float x = 0.f, y = 0.f;
            if (p < cnt) {
                const float* ip = inputs + (size_t)(base + p) * 3;
                x = ip[0]; y = ip[1];
            }
            float feat[32];
            float x64 = 0.0f;
            if (p < cnt) {
                const float u = __fadd_rn(__fdiv_rn(x, 30.0f), 0.5f);
                const float v = __fadd_rn(__fdiv_rn(y, 30.0f), 0.5f);
                const float2* tb = reinterpret_cast<const float2*>(tables);
                #pragma unroll
                for (int l = 0; l < NLEV; l++) {
                    float s  = P.scale[l];
                    float px = __fadd_rn(__fmul_rn(u, s), 0.5f);
                    float py = __fadd_rn(__fmul_rn(v, s), 0.5f);
                    float fx = floorf(px), fy = floorf(py);
                    float wx = px - fx,    wy = py - fy;
                    int ix = (int)fx, iy = (int)fy;
                    int i00, i10, i01, i11;
                    if (P.dense[l]) {
                        int r = P.res[l];
                        i00 = ix + iy * r;  i10 = i00 + 1;
                        i01 = i00 + r;      i11 = i01 + 1;
                        i00 = min(max(i00, 0), TSZ - 1);
                        i10 = min(max(i10, 0), TSZ - 1);
                        i01 = min(max(i01, 0), TSZ - 1);
                        i11 = min(max(i11, 0), TSZ - 1);
                    } else {
                        unsigned ux = (unsigned)ix, uy = (unsigned)iy;
                        unsigned hy0 = uy * HASH_PRIME;
                        unsigned hy1 = (uy + 1u) * HASH_PRIME;
                        i00 = (int)((ux        ^ hy0) & TMASK);
                        i10 = (int)(((ux + 1u) ^ hy0) & TMASK);
                        i01 = (int)((ux        ^ hy1) & TMASK);
                        i11 = (int)(((ux + 1u) ^ hy1) & TMASK);
                    }
                    const float2* t = tb + (size_t)l * TSZ;
                    float2 f00 = __ldg(t + i00);
                    float2 f10 = __ldg(t + i10);
                    float2 f01 = __ldg(t + i01);
                    float2 f11 = __ldg(t + i11);
                    float omx = 1.0f - wx, omy = 1.0f - wy;
                    feat[2 * l]     = (f00.x * omx + f10.x * wx) * omy + (f01.x * omx + f11.x * wx) * wy;
                    feat[2 * l + 1] = (f00.y * omx + f10.y * wx) * omy + (f01.y * omx + f11.y * wx) * wy;
                }
            } else {
                #pragma unroll
                for (int k = 0; k < 32; k++) feat[k] = 0.0f;
            }
            #pragma unroll
            for (int k = 0; k < 32; k++) {
                featT[k * ACT_STRIDE + p] = feat[k];
                x64 += feat[k] * sw[OFF_WT + k * 68 + 64];
            }
            sX64[p] = x64 + sw[OFF_BT + 64];
        }
        bar_crew1();                  // featT complete for all 128 points

        // --- GEMM3: feat @ wt[:,0:64], overlapped with crew0's GEMM2 ---
        #pragma unroll
        for (int q = 0; q < 32; q++) acc3[q] = 0ull;
        gemm88<32, 68, 8>(acc3, featT, sw + OFF_WT, pgB, cgB);
    }
    __syncthreads();   // join: sPZ/sX64 ready; h1T/encT/featT reads all done

    // =======================================================================
    // Assembly: crew1 writes its 8pt x 8col tiles; crew0 writes col 64
    // =======================================================================
    {
        float* ost = actT;
        if (tid >= 128) {
            const int m   = tid - 128;
            const int pgB = m >> 3;
            const int cgB = m & 7;
            #pragma unroll
            for (int c = 0; c < 8; c++) {
                const int col = cgB * 8 + c;
                const float bias = sw[OFF_BT + col];
                #pragma unroll
                for (int p2 = 0; p2 < 4; p2++) {
                    float a, b; unpack2(acc3[p2 * 8 + c], a, b);
                    const int pt = pgB * 8 + 2 * p2;
                    if (col == 0) {
                        ost[pt * 65]       = sPZ[pt] - a;
                        ost[(pt + 1) * 65] = sPZ[pt + 1] - b;
                    } else {
                        ost[pt * 65 + col]       = a + bias;
                        ost[(pt + 1) * 65 + col] = b + bias;
                    }
                }
            }
        } else {
            ost[tid * 65 + 64] = sX64[tid];
        }
    }
    __syncthreads();

    // ---- coalesced flush ----
    if (cnt == 128) {
        float4* o4 = reinterpret_cast<float4*>(out + (size_t)base * 65);
        const float4* s4 = reinterpret_cast<const float4*>(actT);
        #pragma unroll
        for (int t = tid; t < (128 * 65) / 4; t += 256) o4[t] = s4[t];
    } else if (cnt > 0) {
        const int tot = cnt * 65;
        for (int t = tid; t < tot; t += 256) out[(size_t)base * 65 + t] = actT[t];
    }
}

// ---------------------------------------------------------------------------
// Launch
// ---------------------------------------------------------------------------
extern "C" void kernel_launch(void* const* d_in, const int* in_sizes, int n_in,
                              void* d_out, int out_size) {
    const float* inputs  = (const float*)d_in[0];
    const float* tables  = (const float*)d_in[1];
    const float* W_tiny  = (const float*)d_in[2];
    const float* b_tiny  = (const float*)d_in[3];
    const float* Wp1     = (const float*)d_in[4];
    const float* Wp2     = (const float*)d_in[5];
    const float* Wp3     = (const float*)d_in[6];
    float* out           = (float*)d_out;

    const int N = in_sizes[0] / 3;

    LevelP P;
    for (int l = 0; l < NLEV; l++) {
        double sc = pow(2.0, (double)l * log2(1.5)) * 16.0 - 1.0;
        int res = (int)ceil(sc) + 1;
        P.scale[l] = (float)sc;
        P.res[l]   = res;
        P.dense[l] = ((long long)res * (long long)res <= (long long)TSZ) ? 1 : 0;
    }

    prep_weights<<<1, 256>>>(W_tiny, b_tiny, Wp1, Wp2, Wp3);

    static int attr_done = 0;
    if (!attr_done) {
        cudaFuncSetAttribute(sdf_kernel,
                             cudaFuncAttributeMaxDynamicSharedMemorySize, SMEM_BYTES);
        attr_done = 1;
    }

    const int tiles = (N + 127) / 128;
    sdf_kernel<<<tiles, 256, SMEM_BYTES>>>(inputs, tables, out, N, P);
}

// round 17
// speedup vs baseline: 1.2122x; 1.0376x over previous
#include <cuda_runtime.h>
#include <cuda_bf16.h>
#include <math.h>

// ---------------------------------------------------------------------------
// Problem constants
// ---------------------------------------------------------------------------
#define NLEV 16
#define TSZ  (1 << 19)
#define TMASK (TSZ - 1)
#define HASH_PRIME 2654435761u

typedef unsigned long long u64;

// Padded weight blob: wp1[12*64] | wp2[64*64] | wp3[64] | wt[32*68] | bt[68]
#define OFF_WP1 0
#define OFF_WP2 768
#define OFF_WP3 4864
#define OFF_WT  4928
#define OFF_BT  7104
#define TOTW    7172

struct __align__(16) Weights {
    float wp1[12 * 64];
    float wp2[64 * 64];
    float wp3[64];
    float wt [32 * 68];
    float bt [68];
};
__device__ Weights g_w;

struct LevelP {
    float scale[NLEV];
    int   res[NLEV];
    int   dense[NLEV];
};

// Shared layout (floats) — R12 champion layout
#define ACT_STRIDE 132
#define ACT_FLOATS  (64 * ACT_STRIDE)     // 8448 (encT/h1T, then out-stage 128*65=8320)
#define FEAT_FLOATS (32 * ACT_STRIDE)     // 4224
#define PAR_STRIDE 130
#define PAR_FLOATS (16 * PAR_STRIDE)      // 2080 (prior partials)
#define SMEM_FLOATS (TOTW + ACT_FLOATS + FEAT_FLOATS + PAR_FLOATS + 128 + 256 + 128)
#define SMEM_BYTES  (SMEM_FLOATS * 4)

// ---------------------------------------------------------------------------
// f32x2 helpers
// ---------------------------------------------------------------------------
__device__ __forceinline__ u64 dup2(float a) {
    u64 r; asm("mov.b64 %0, {%1, %1};" : "=l"(r) : "f"(a)); return r;
}
__device__ __forceinline__ u64 pack2(float a, float b) {
    u64 r; asm("mov.b64 %0, {%1, %2};" : "=l"(r) : "f"(a), "f"(b)); return r;
}
__device__ __forceinline__ void unpack2(u64 v, float &a, float &b) {
    asm("mov.b64 {%0, %1}, %2;" : "=f"(a), "=f"(b) : "l"(v));
}
__device__ __forceinline__ void fma2(u64 &d, u64 a, u64 b) {
    asm("fma.rn.f32x2 %0, %1, %2, %0;" : "+l"(d) : "l"(a), "l"(b));
}
__device__ __forceinline__ float sigm(float x) {
    return __fdividef(1.0f, 1.0f + __expf(-x));
}

// ---------------------------------------------------------------------------
// Register-tiled GEMM accumulate with k+1 prefetch (champion version)
// Thread (pg,cg): points [pg*8,+8) x cols [cg*4,+4);  acc[p2*4+c].
// Prefetch reads one row past K — always lands in valid smem (value unused).
// ---------------------------------------------------------------------------
template <int K, int NC>
__device__ __forceinline__ void gemm_acc(u64* __restrict__ acc,
                                         const float* __restrict__ aT,
                                         const float* __restrict__ B,
                                         int pg, int cg) {
    const float* arow = aT + pg * 8;
    const float* brow = B + cg * 4;
    ulonglong2 a01 = *reinterpret_cast<const ulonglong2*>(arow);
    ulonglong2 a23 = *reinterpret_cast<const ulonglong2*>(arow + 4);
    float4 b4 = *reinterpret_cast<const float4*>(brow);
    #pragma unroll 8
    for (int k = 0; k < K; k++) {
        const float* an = arow + (k + 1) * ACT_STRIDE;
        ulonglong2 na01 = *reinterpret_cast<const ulonglong2*>(an);
        ulonglong2 na23 = *reinterpret_cast<const ulonglong2*>(an + 4);
        float4 nb4 = *reinterpret_cast<const float4*>(brow + (k + 1) * NC);
        u64 b0 = dup2(b4.x), b1 = dup2(b4.y), b2 = dup2(b4.z), b3 = dup2(b4.w);
        u64 a[4] = {a01.x, a01.y, a23.x, a23.y};
        #pragma unroll
        for (int p = 0; p < 4; p++) {
            fma2(acc[p * 4 + 0], a[p], b0);
            fma2(acc[p * 4 + 1], a[p], b1);
            fma2(acc[p * 4 + 2], a[p], b2);
            fma2(acc[p * 4 + 3], a[p], b3);
        }
        a01 = na01; a23 = na23; b4 = nb4;
    }
}

// ---------------------------------------------------------------------------
// Prep kernel: pack weights into padded blob
// ---------------------------------------------------------------------------
__global__ void prep_weights(const float* __restrict__ W_tiny,
                             const float* __restrict__ b_tiny,
                             const float* __restrict__ Wp1,
                             const float* __restrict__ Wp2,
                             const float* __restrict__ Wp3) {
    int t = threadIdx.x;
    for (int i = t; i < 12 * 64; i += blockDim.x) g_w.wp1[i] = Wp1[i];
    for (int i = t; i < 64 * 64; i += blockDim.x) g_w.wp2[i] = Wp2[i];
    if (t < 64) g_w.wp3[t] = Wp3[t];
    for (int i = t; i < 32 * 68; i += blockDim.x) {
        int k = i / 68, j = i % 68;
        g_w.wt[i] = (j < 65) ? W_tiny[k * 65 + j] : 0.0f;
    }
    if (t < 68) g_w.bt[t] = (t < 65) ? b_tiny[t] : 0.0f;
}

// ---------------------------------------------------------------------------
// Fused kernel: R12 champion structure, fast-MUFU sincos
// ---------------------------------------------------------------------------
__global__ void __launch_bounds__(256, 2)
sdf_kernel(const float* __restrict__ inputs,
           const float* __restrict__ tables,
           float* __restrict__ out,
           int N, LevelP P) {
    extern __shared__ float smem[];
    float* sw    = smem;                      // weights blob (28.7 KB)
    float* actT  = sw + TOTW;                 // encT rows 0-11 / h1T rows 0-63 / out-stage
    float* featT = actT + ACT_FLOATS;         // [32][132]
    float* sPar  = featT + FEAT_FLOATS;       // [16][130] prior partials
    float* sZ    = sPar + PAR_FLOATS;         // [128]
    float* sX64  = sZ + 128;                  // [256] (two halves)
    float* sPZ   = sX64 + 256;                // [128]

    const int tid = threadIdx.x;
    const int pg  = tid >> 4;                 // 16 point-groups of 8 pts
    const int cg  = tid & 15;                 // 16 col-groups of 4 cols
    const int base = blockIdx.x * 128;
    const int cnt  = min(128, N - base);

    // ---- cooperative weight load ----
    {
        const float4* src = reinterpret_cast<const float4*>(g_w.wp1);
        float4* dst = reinterpret_cast<float4*>(sw);
        #pragma unroll
        for (int i = tid; i < TOTW / 4; i += 256) dst[i] = src[i];
    }
    __syncthreads();

    // =======================================================================
    // Split scalar phase: 2 threads per point.
    //   half 0 -> x-sincos (encT rows 0-5)  + even hash levels
    //   half 1 -> y-sincos (encT rows 6-11) + odd  hash levels
    // =======================================================================
    {
        const int half = tid >> 7;            // warps 0-3 = half0, 4-7 = half1
        const int p    = tid & 127;
        float x = 0.f, y = 0.f;
        if (p < cnt) {
            const float* ip = inputs + (size_t)(base + p) * 3;
            x = ip[0]; y = ip[1];
            if (half == 0) sZ[p] = ip[2];
        } else if (half == 0) sZ[p] = 0.f;

        // fast-MUFU sincos for this half's coordinate (rel_err budget 1e-3;
        // MUFU.SIN error ~1e-6 at |arg|<=4pi*|coord| is far inside budget)
        {
            const float PIF = 3.14159265358979323846f;
            const float cc = (half == 0) ? x : y;
            float s0, c0, s1, c1, s2, c2;
            __sincosf(cc * PIF,          &s0, &c0);
            __sincosf(cc * (2.0f * PIF), &s1, &c1);
            __sincosf(cc * (4.0f * PIF), &s2, &c2);
            float* eb = actT + half * 6 * ACT_STRIDE + p;
            if (p < cnt) {
                eb[0 * ACT_STRIDE] = s0; eb[1 * ACT_STRIDE] = s1; eb[2 * ACT_STRIDE] = s2;
                eb[3 * ACT_STRIDE] = c0; eb[4 * ACT_STRIDE] = c1; eb[5 * ACT_STRIDE] = c2;
            } else {
                eb[0 * ACT_STRIDE] = 0.f; eb[1 * ACT_STRIDE] = 0.f; eb[2 * ACT_STRIDE] = 0.f;
                eb[3 * ACT_STRIDE] = 0.f; eb[4 * ACT_STRIDE] = 0.f; eb[5 * ACT_STRIDE] = 0.f;
            }
        }

        // 8 hash levels (parity split), featT written in-loop, x64 incremental
        float x64 = 0.0f;
        if (p < cnt) {
            const float u = __fadd_rn(__fdiv_rn(x, 30.0f), 0.5f);
            const float v = __fadd_rn(__fdiv_rn(y, 30.0f), 0.5f);
            const float2* tb = reinterpret_cast<const float2*>(tables);
            #pragma unroll
            for (int i = 0; i < 8; i++) {
                const int l = 2 * i + half;
                float s  = P.scale[l];
                float px = __fadd_rn(__fmul_rn(u, s), 0.5f);
                float py = __fadd_rn(__fmul_rn(v, s), 0.5f);
                float fx = floorf(px), fy = floorf(py);
                float wx = px - fx,    wy = py - fy;
                int ix = (int)fx, iy = (int)fy;
                int i00, i10, i01, i11;
                if (P.dense[l]) {
                    int r = P.res[l];
                    i00 = ix + iy * r;  i10 = i00 + 1;
                    i01 = i00 + r;      i11 = i01 + 1;
                    i00 = min(max(i00, 0), TSZ - 1);
                    i10 = min(max(i10, 0), TSZ - 1);
                    i01 = min(max(i01, 0), TSZ - 1);
                    i11 = min(max(i11, 0), TSZ - 1);
                } else {
                    unsigned ux = (unsigned)ix, uy = (unsigned)iy;
                    unsigned hy0 = uy * HASH_PRIME;
                    unsigned hy1 = (uy + 1u) * HASH_PRIME;
                    i00 = (int)((ux        ^ hy0) & TMASK);
                    i10 = (int)(((ux + 1u) ^ hy0) & TMASK);
                    i01 = (int)((ux        ^ hy1) & TMASK);
                    i11 = (int)(((ux + 1u) ^ hy1) & TMASK);
                }
                const float2* t = tb + (size_t)l * TSZ;
                float2 f00 = __ldg(t + i00);
                float2 f10 = __ldg(t + i10);
                float2 f01 = __ldg(t + i01);
                float2 f11 = __ldg(t + i11);
                float omx = 1.0f - wx, omy = 1.0f - wy;
                float g0 = (f00.x * omx + f10.x * wx) * omy + (f01.x * omx + f11.x * wx) * wy;
                float g1 = (f00.y * omx + f10.y * wx) * omy + (f01.y * omx + f11.y * wx) * wy;
                featT[(2 * l) * ACT_STRIDE + p]     = g0;
                featT[(2 * l + 1) * ACT_STRIDE + p] = g1;
                x64 += g0 * sw[OFF_WT + (2 * l) * 68 + 64];
                x64 += g1 * sw[OFF_WT + (2 * l + 1) * 68 + 64];
            }
        } else {
            #pragma unroll
            for (int i = 0; i < 8; i++) {
                const int l = 2 * i + half;
                featT[(2 * l) * ACT_STRIDE + p]     = 0.f;
                featT[(2 * l + 1) * ACT_STRIDE + p] = 0.f;
            }
        }
        sX64[half * 128 + p] = x64;
    }
    __syncthreads();

    u64 acc[16];

    // ---- GEMM1: h1 = sigmoid(enc @ Wp1)  [128,12]x[12,64] ----
    #pragma unroll
    for (int q = 0; q < 16; q++) acc[q] = 0ull;
    gemm_acc<12, 64>(acc, actT, sw + OFF_WP1, pg, cg);
    __syncthreads();                          // encT reads done; actT -> h1T
    #pragma unroll
    for (int c = 0; c < 4; c++) {
        float* row = actT + (cg * 4 + c) * ACT_STRIDE + pg * 8;
        #pragma unroll
        for (int p2 = 0; p2 < 4; p2++) {
            float a, b; unpack2(acc[p2 * 4 + c], a, b);
            *reinterpret_cast<u64*>(row + 2 * p2) = pack2(sigm(a), sigm(b));
        }
    }
    __syncthreads();

    // ---- GEMM2: h2 = sigmoid(h1 @ Wp2); prior partials via wp3 ----
    #pragma unroll
    for (int q = 0; q < 16; q++) acc[q] = 0ull;
    gemm_acc<64, 64>(acc, actT, sw + OFF_WP2, pg, cg);
    {
        float* prow = sPar + cg * PAR_STRIDE + pg * 8;
        #pragma unroll
        for (int p2 = 0; p2 < 4; p2++) {
            float pa = 0.f, pb = 0.f;
            #pragma unroll
            for (int c = 0; c < 4; c++) {
                float w3 = sw[OFF_WP3 + cg * 4 + c];
                float a, b; unpack2(acc[p2 * 4 + c], a, b);
                pa += sigm(a) * w3;
                pb += sigm(b) * w3;
            }
            *reinterpret_cast<u64*>(prow + 2 * p2) = pack2(pa, pb);
        }
    }
    __syncthreads();                          // h1T reads done; sPar ready

    // ---- prior reduction + x64 combine (half threads) + GEMM3 ----
    if (tid < 128) {
        float pr = 0.0f;
        #pragma unroll
        for (int c = 0; c < 16; c++) pr += sPar[c * PAR_STRIDE + tid];
        sPZ[tid] = (sZ[tid] - sw[OFF_BT]) - pr;   // z - bt0 - prior
        sX64[tid] = sX64[tid] + sX64[128 + tid] + sw[OFF_BT + 64];
    }
    #pragma unroll
    for (int q = 0; q < 16; q++) acc[q] = 0ull;
    gemm_acc<32, 68>(acc, featT, sw + OFF_WT, pg, cg);
    __syncthreads();                          // featT/h1T dead; sPZ/sX64 ready

    // ---- assemble output rows [128][65] in shared ----
    {
        float* ost = actT;
        #pragma unroll
        for (int c = 0; c < 4; c++) {
            const int col = cg * 4 + c;
            const float bias = sw[OFF_BT + col];
            #pragma unroll
            for (int p2 = 0; p2 < 4; p2++) {
                float a, b; unpack2(acc[p2 * 4 + c], a, b);
                int pA = pg * 8 + 2 * p2;
                if (col == 0) {
                    ost[pA * 65]       = sPZ[pA] - a;
                    ost[(pA + 1) * 65] = sPZ[pA + 1] - b;
                } else {
                    ost[pA * 65 + col]       = a + bias;
                    ost[(pA + 1) * 65 + col] = b + bias;
                }
            }
        }
        if (tid < 128) ost[tid * 65 + 64] = sX64[tid];
    }
    __syncthreads();

    // ---- coalesced flush ----
    if (cnt == 128) {
        float4* o4 = reinterpret_cast<float4*>(out + (size_t)base * 65);
        const float4* s4 = reinterpret_cast<const float4*>(actT);
        #pragma unroll
        for (int t = tid; t < (128 * 65) / 4; t += 256) o4[t] = s4[t];
    } else if (cnt > 0) {
        const int tot = cnt * 65;
        for (int t = tid; t < tot; t += 256) out[(size_t)base * 65 + t] = actT[t];
    }
}

// ---------------------------------------------------------------------------
// Launch
// ---------------------------------------------------------------------------
extern "C" void kernel_launch(void* const* d_in, const int* in_sizes, int n_in,
                              void* d_out, int out_size) {
    const float* inputs  = (const float*)d_in[0];
    const float* tables  = (const float*)d_in[1];
    const float* W_tiny  = (const float*)d_in[2];
    const float* b_tiny  = (const float*)d_in[3];
    const float* Wp1     = (const float*)d_in[4];
    const float* Wp2     = (const float*)d_in[5];
    const float* Wp3     = (const float*)d_in[6];
    float* out           = (float*)d_out;

    const int N = in_sizes[0] / 3;

    LevelP P;
    for (int l = 0; l < NLEV; l++) {
        double sc = pow(2.0, (double)l * log2(1.5)) * 16.0 - 1.0;
        int res = (int)ceil(sc) + 1;
        P.scale[l] = (float)sc;
        P.res[l]   = res;
        P.dense[l] = ((long long)res * (long long)res <= (long long)TSZ) ? 1 : 0;
    }

    prep_weights<<<1, 256>>>(W_tiny, b_tiny, Wp1, Wp2, Wp3);

    static int attr_done = 0;
    if (!attr_done) {
        cudaFuncSetAttribute(sdf_kernel,
                             cudaFuncAttributeMaxDynamicSharedMemorySize, SMEM_BYTES);
        attr_done = 1;
    }

    const int tiles = (N + 127) / 128;
    sdf_kernel<<<tiles, 256, SMEM_BYTES>>>(inputs, tables, out, N, P);
}